// round 1
// baseline (speedup 1.0000x reference)
#include <cuda_runtime.h>

typedef unsigned long long ull;

#define NFEATS 131072
#define INS    256
#define HID    1024
#define OUTS   256
#define NEXP   16

#define TILE_M 128
#define THREADS 512
#define XSTR 260   // padded X row stride (floats) to kill bank conflicts
#define HSTR 66    // padded H row stride

// -------- routing scratch (device globals; no allocation allowed) --------
__device__ int d_perm[NFEATS];
__device__ int d_counts[NEXP];
__device__ int d_offsets[NEXP + 1];
__device__ int d_cursor[NEXP];
__device__ int d_wide;   // 1 if module_ids is int64, 0 if int32

// Detect int64 vs int32 ids: int64 little-endian => every odd 32-bit word of
// first 64 words is the (zero) high half. False positive prob (1/16)^32 ~ 0.
__global__ void k_detect(const int* __restrict__ ids) {
    int wide = 1;
    for (int i = 1; i < 64; i += 2) if (ids[i] != 0) { wide = 0; break; }
    d_wide = wide;
    for (int e = 0; e < NEXP; e++) d_counts[e] = 0;
}

__global__ void k_hist(const int* __restrict__ ids) {
    __shared__ int cnt[NEXP];
    int t = threadIdx.x;
    if (t < NEXP) cnt[t] = 0;
    __syncthreads();
    int i = blockIdx.x * blockDim.x + t;
    int wide = d_wide;
    int id = wide ? ids[2 * i] : ids[i];
    atomicAdd(&cnt[id], 1);
    __syncthreads();
    if (t < NEXP) atomicAdd(&d_counts[t], cnt[t]);
}

__global__ void k_scan() {
    int s = 0;
    for (int e = 0; e < NEXP; e++) { d_offsets[e] = s; d_cursor[e] = s; s += d_counts[e]; }
    d_offsets[NEXP] = s;
}

__global__ void k_scatter(const int* __restrict__ ids) {
    __shared__ int lcnt[NEXP];
    __shared__ int lbase[NEXP];
    int t = threadIdx.x;
    if (t < NEXP) lcnt[t] = 0;
    __syncthreads();
    int i = blockIdx.x * blockDim.x + t;
    int wide = d_wide;
    int id = wide ? ids[2 * i] : ids[i];
    int r = atomicAdd(&lcnt[id], 1);
    __syncthreads();
    if (t < NEXP) lbase[t] = atomicAdd(&d_cursor[t], lcnt[t]);
    __syncthreads();
    d_perm[lbase[id] + r] = i;
}

// -------- packed f32x2 helpers (FFMA2: 2x fp32 FMA rate on sm_103a) --------
__device__ __forceinline__ ull pack2(float a, float b) {
    ull r; asm("mov.b64 %0, {%1,%2};" : "=l"(r) : "f"(a), "f"(b)); return r;
}
__device__ __forceinline__ void unpack2(ull v, float& a, float& b) {
    asm("mov.b64 {%0,%1}, %2;" : "=f"(a), "=f"(b) : "l"(v));
}
__device__ __forceinline__ ull ffma2(ull a, ull b, ull c) {
    ull d; asm("fma.rn.f32x2 %0, %1, %2, %3;" : "=l"(d) : "l"(a), "l"(b), "l"(c)); return d;
}

// -------- fused 2-layer expert MLP on a 128-token tile --------
// Thread layout: 512 threads = 32 (tm: 4 rows each) x 16 (tn: cols tn*2+32j).
// Hidden processed in 16 chunks of 64; H chunk lives only in smem.
// Y accumulated in registers (4 rows x 8 float2 pairs per thread).
__global__ __launch_bounds__(THREADS, 1)
void k_moe(const float* __restrict__ X, const float* __restrict__ W1,
           const float* __restrict__ B1, const float* __restrict__ W2,
           const float* __restrict__ B2, float* __restrict__ Y)
{
    const int e = blockIdx.y;
    const int start = d_offsets[e];
    const int count = d_offsets[e + 1] - start;
    const int m0 = blockIdx.x * TILE_M;
    if (m0 >= count) return;
    const int valid = min(TILE_M, count - m0);

    extern __shared__ float sm[];
    float* Xs  = sm;                          // TILE_M * XSTR
    float* Hs  = Xs + TILE_M * XSTR;          // TILE_M * HSTR
    float* W1s = Hs + TILE_M * HSTR;          // 32 * 64
    float* W2s = W1s + 32 * 64;               // 16 * 256
    float* b1s = W2s + 16 * 256;              // 64
    float* b2s = b1s + 64;                    // 256
    __shared__ int rowtok[TILE_M];

    const int tid = threadIdx.x;
    const int tm = tid >> 4;     // 0..31
    const int tn = tid & 15;     // 0..15

    if (tid < TILE_M)
        rowtok[tid] = (tid < valid) ? d_perm[start + m0 + tid] : -1;
    if (tid < OUTS / 4)
        *(float4*)&b2s[tid * 4] = *(const float4*)&B2[e * OUTS + tid * 4];
    __syncthreads();

    // Gather X tile into smem (zeros for padded rows)
    for (int idx = tid; idx < TILE_M * (INS / 4); idx += THREADS) {
        int row = idx >> 6, c4 = idx & 63;
        float4 v = make_float4(0.f, 0.f, 0.f, 0.f);
        int tok = rowtok[row];
        if (tok >= 0) v = ((const float4*)X)[(size_t)tok * (INS / 4) + c4];
        *(float4*)&Xs[row * XSTR + c4 * 4] = v;
    }

    ull yacc[4][8];
    #pragma unroll
    for (int i = 0; i < 4; i++)
        #pragma unroll
        for (int j = 0; j < 8; j++) yacc[i][j] = 0ull;

    #pragma unroll 1
    for (int ch = 0; ch < HID / 64; ch++) {
        const int h0 = ch * 64;
        if (tid < 16)
            *(float4*)&b1s[tid * 4] = *(const float4*)&B1[e * HID + h0 + tid * 4];

        ull acc[4][2];
        #pragma unroll
        for (int i = 0; i < 4; i++) { acc[i][0] = 0ull; acc[i][1] = 0ull; }

        // ---- phase 1: H[128x64] = relu(X[128x256] @ W1[:,h0:h0+64] + b1) ----
        #pragma unroll 1
        for (int kt = 0; kt < INS / 32; kt++) {
            const int k0 = kt * 32;
            __syncthreads();   // W1s reuse + (first iter) Xs/b1s visibility
            {
                int kk = tid >> 4, f4 = tid & 15;
                *(float4*)&W1s[kk * 64 + f4 * 4] =
                    *(const float4*)&W1[(size_t)(e * INS + k0 + kk) * HID + h0 + f4 * 4];
            }
            __syncthreads();
            #pragma unroll
            for (int kk4 = 0; kk4 < 8; kk4++) {
                float4 xv[4];
                #pragma unroll
                for (int i = 0; i < 4; i++)
                    xv[i] = *(const float4*)&Xs[(tm * 4 + i) * XSTR + k0 + kk4 * 4];
                #pragma unroll
                for (int u = 0; u < 4; u++) {
                    const int kk = kk4 * 4 + u;
                    ull w0 = *(const ull*)&W1s[kk * 64 + tn * 2];
                    ull w1 = *(const ull*)&W1s[kk * 64 + tn * 2 + 32];
                    #pragma unroll
                    for (int i = 0; i < 4; i++) {
                        float x = (u == 0) ? xv[i].x : (u == 1) ? xv[i].y
                                : (u == 2) ? xv[i].z : xv[i].w;
                        ull xx = pack2(x, x);
                        acc[i][0] = ffma2(xx, w0, acc[i][0]);
                        acc[i][1] = ffma2(xx, w1, acc[i][1]);
                    }
                }
            }
        }
        // bias + relu -> Hs
        #pragma unroll
        for (int i = 0; i < 4; i++) {
            int row = tm * 4 + i;
            #pragma unroll
            for (int j = 0; j < 2; j++) {
                int col = tn * 2 + 32 * j;
                float a0, a1; unpack2(acc[i][j], a0, a1);
                float2 hv;
                hv.x = fmaxf(a0 + b1s[col], 0.f);
                hv.y = fmaxf(a1 + b1s[col + 1], 0.f);
                *(float2*)&Hs[row * HSTR + col] = hv;
            }
        }

        // ---- phase 2: Y += H[128x64] @ W2[h0:h0+64, :] ----
        #pragma unroll 1
        for (int ht = 0; ht < 4; ht++) {
            __syncthreads();   // Hs visible (first iter) + W2s reuse
            {
                int hr = tid >> 5, f4 = tid & 31;
                const float* src = &W2[(size_t)(e * HID + h0 + ht * 16 + hr) * OUTS];
                *(float4*)&W2s[hr * 256 + f4 * 4]        = *(const float4*)&src[f4 * 4];
                *(float4*)&W2s[hr * 256 + (f4 + 32) * 4] = *(const float4*)&src[(f4 + 32) * 4];
            }
            __syncthreads();
            #pragma unroll
            for (int h = 0; h < 16; h++) {
                ull wv[8];
                #pragma unroll
                for (int j = 0; j < 8; j++)
                    wv[j] = *(const ull*)&W2s[h * 256 + tn * 2 + 32 * j];
                #pragma unroll
                for (int i = 0; i < 4; i++) {
                    float x = Hs[(tm * 4 + i) * HSTR + ht * 16 + h];
                    ull xx = pack2(x, x);
                    #pragma unroll
                    for (int j = 0; j < 8; j++)
                        yacc[i][j] = ffma2(xx, wv[j], yacc[i][j]);
                }
            }
        }
    }

    // ---- epilogue: + b2, scatter back ----
    #pragma unroll
    for (int i = 0; i < 4; i++) {
        int row = tm * 4 + i;
        if (row < valid) {
            float* dst = Y + (size_t)rowtok[row] * OUTS;
            #pragma unroll
            for (int j = 0; j < 8; j++) {
                int col = tn * 2 + 32 * j;
                float y0, y1; unpack2(yacc[i][j], y0, y1);
                float2 o; o.x = y0 + b2s[col]; o.y = y1 + b2s[col + 1];
                *(float2*)&dst[col] = o;
            }
        }
    }
}

extern "C" void kernel_launch(void* const* d_in, const int* in_sizes, int n_in,
                              void* d_out, int out_size) {
    const float* X  = (const float*)d_in[0];
    const float* W1 = (const float*)d_in[1];
    const float* B1 = (const float*)d_in[2];
    const float* W2 = (const float*)d_in[3];
    const float* B2 = (const float*)d_in[4];
    const int*   ids = (const int*)d_in[5];   // int32 or int64; detected on device
    float* Y = (float*)d_out;

    k_detect<<<1, 1>>>(ids);
    k_hist<<<NFEATS / 256, 256>>>(ids);
    k_scan<<<1, 1>>>();
    k_scatter<<<NFEATS / 256, 256>>>(ids);

    size_t smem = (size_t)(TILE_M * XSTR + TILE_M * HSTR + 32 * 64 + 16 * 256 + 64 + 256) * sizeof(float);
    cudaFuncSetAttribute(k_moe, cudaFuncAttributeMaxDynamicSharedMemorySize, (int)smem);

    dim3 grid(NFEATS / TILE_M, NEXP);   // worst-case tiles per expert; empties exit fast
    k_moe<<<grid, THREADS, smem>>>(X, W1, B1, W2, B2, Y);
}

// round 2
// speedup vs baseline: 1.0087x; 1.0087x over previous
#include <cuda_runtime.h>

typedef unsigned long long ull;

#define NFEATS 131072
#define INS    256
#define HID    1024
#define OUTS   256
#define NEXP   16

#define TILE_M 128
#define THREADS 512
#define XSTR 260   // padded X row stride (floats) to kill bank conflicts
#define HSTR 66    // padded H row stride

// -------- routing scratch (device globals; no allocation allowed) --------
__device__ int d_perm[NFEATS];
__device__ int d_counts[NEXP];
__device__ int d_offsets[NEXP + 1];
__device__ int d_cursor[NEXP];
__device__ int d_wide;   // 1 if module_ids is int64, 0 if int32

// Detect int64 vs int32 ids: int64 little-endian => every odd 32-bit word of
// first 64 words is the (zero) high half. False positive prob (1/16)^32 ~ 0.
__global__ void k_detect(const int* __restrict__ ids) {
    int wide = 1;
    for (int i = 1; i < 64; i += 2) if (ids[i] != 0) { wide = 0; break; }
    d_wide = wide;
    for (int e = 0; e < NEXP; e++) d_counts[e] = 0;
}

__global__ void k_hist(const int* __restrict__ ids) {
    __shared__ int cnt[NEXP];
    int t = threadIdx.x;
    if (t < NEXP) cnt[t] = 0;
    __syncthreads();
    int i = blockIdx.x * blockDim.x + t;
    int wide = d_wide;
    int id = wide ? ids[2 * i] : ids[i];
    atomicAdd(&cnt[id], 1);
    __syncthreads();
    if (t < NEXP) atomicAdd(&d_counts[t], cnt[t]);
}

__global__ void k_scan() {
    int s = 0;
    for (int e = 0; e < NEXP; e++) { d_offsets[e] = s; d_cursor[e] = s; s += d_counts[e]; }
    d_offsets[NEXP] = s;
}

__global__ void k_scatter(const int* __restrict__ ids) {
    __shared__ int lcnt[NEXP];
    __shared__ int lbase[NEXP];
    int t = threadIdx.x;
    if (t < NEXP) lcnt[t] = 0;
    __syncthreads();
    int i = blockIdx.x * blockDim.x + t;
    int wide = d_wide;
    int id = wide ? ids[2 * i] : ids[i];
    int r = atomicAdd(&lcnt[id], 1);
    __syncthreads();
    if (t < NEXP) lbase[t] = atomicAdd(&d_cursor[t], lcnt[t]);
    __syncthreads();
    d_perm[lbase[id] + r] = i;
}

// -------- packed f32x2 helpers (FFMA2: 2x fp32 FMA rate on sm_103a) --------
__device__ __forceinline__ ull pack2(float a, float b) {
    ull r; asm("mov.b64 %0, {%1,%2};" : "=l"(r) : "f"(a), "f"(b)); return r;
}
__device__ __forceinline__ void unpack2(ull v, float& a, float& b) {
    asm("mov.b64 {%0,%1}, %2;" : "=f"(a), "=f"(b) : "l"(v));
}
__device__ __forceinline__ ull ffma2(ull a, ull b, ull c) {
    ull d; asm("fma.rn.f32x2 %0, %1, %2, %3;" : "=l"(d) : "l"(a), "l"(b), "l"(c)); return d;
}

// -------- fused 2-layer expert MLP on a 128-token tile --------
// Thread layout: 512 threads = 32 (tm: 4 rows each) x 16 (tn: cols tn*2+32j).
// Hidden processed in 16 chunks of 64; H chunk lives only in smem.
// Y accumulated in registers (4 rows x 8 float2 pairs per thread).
__global__ __launch_bounds__(THREADS, 1)
void k_moe(const float* __restrict__ X, const float* __restrict__ W1,
           const float* __restrict__ B1, const float* __restrict__ W2,
           const float* __restrict__ B2, float* __restrict__ Y)
{
    const int e = blockIdx.y;
    const int start = d_offsets[e];
    const int count = d_offsets[e + 1] - start;
    const int m0 = blockIdx.x * TILE_M;
    if (m0 >= count) return;
    const int valid = min(TILE_M, count - m0);

    extern __shared__ float sm[];
    float* Xs  = sm;                          // TILE_M * XSTR
    float* Hs  = Xs + TILE_M * XSTR;          // TILE_M * HSTR
    float* W1s = Hs + TILE_M * HSTR;          // 32 * 64
    float* W2s = W1s + 32 * 64;               // 16 * 256
    float* b1s = W2s + 16 * 256;              // 64
    float* b2s = b1s + 64;                    // 256
    __shared__ int rowtok[TILE_M];

    const int tid = threadIdx.x;
    const int tm = tid >> 4;     // 0..31
    const int tn = tid & 15;     // 0..15

    if (tid < TILE_M)
        rowtok[tid] = (tid < valid) ? d_perm[start + m0 + tid] : -1;
    if (tid < OUTS / 4)
        *(float4*)&b2s[tid * 4] = *(const float4*)&B2[e * OUTS + tid * 4];
    __syncthreads();

    // Gather X tile into smem (zeros for padded rows)
    for (int idx = tid; idx < TILE_M * (INS / 4); idx += THREADS) {
        int row = idx >> 6, c4 = idx & 63;
        float4 v = make_float4(0.f, 0.f, 0.f, 0.f);
        int tok = rowtok[row];
        if (tok >= 0) v = ((const float4*)X)[(size_t)tok * (INS / 4) + c4];
        *(float4*)&Xs[row * XSTR + c4 * 4] = v;
    }

    ull yacc[4][8];
    #pragma unroll
    for (int i = 0; i < 4; i++)
        #pragma unroll
        for (int j = 0; j < 8; j++) yacc[i][j] = 0ull;

    #pragma unroll 1
    for (int ch = 0; ch < HID / 64; ch++) {
        const int h0 = ch * 64;
        if (tid < 16)
            *(float4*)&b1s[tid * 4] = *(const float4*)&B1[e * HID + h0 + tid * 4];

        ull acc[4][2];
        #pragma unroll
        for (int i = 0; i < 4; i++) { acc[i][0] = 0ull; acc[i][1] = 0ull; }

        // ---- phase 1: H[128x64] = relu(X[128x256] @ W1[:,h0:h0+64] + b1) ----
        #pragma unroll 1
        for (int kt = 0; kt < INS / 32; kt++) {
            const int k0 = kt * 32;
            __syncthreads();   // W1s reuse + (first iter) Xs/b1s visibility
            {
                int kk = tid >> 4, f4 = tid & 15;
                *(float4*)&W1s[kk * 64 + f4 * 4] =
                    *(const float4*)&W1[(size_t)(e * INS + k0 + kk) * HID + h0 + f4 * 4];
            }
            __syncthreads();
            #pragma unroll
            for (int kk4 = 0; kk4 < 8; kk4++) {
                float4 xv[4];
                #pragma unroll
                for (int i = 0; i < 4; i++)
                    xv[i] = *(const float4*)&Xs[(tm * 4 + i) * XSTR + k0 + kk4 * 4];
                #pragma unroll
                for (int u = 0; u < 4; u++) {
                    const int kk = kk4 * 4 + u;
                    ull w0 = *(const ull*)&W1s[kk * 64 + tn * 2];
                    ull w1 = *(const ull*)&W1s[kk * 64 + tn * 2 + 32];
                    #pragma unroll
                    for (int i = 0; i < 4; i++) {
                        float x = (u == 0) ? xv[i].x : (u == 1) ? xv[i].y
                                : (u == 2) ? xv[i].z : xv[i].w;
                        ull xx = pack2(x, x);
                        acc[i][0] = ffma2(xx, w0, acc[i][0]);
                        acc[i][1] = ffma2(xx, w1, acc[i][1]);
                    }
                }
            }
        }
        // bias + relu -> Hs
        #pragma unroll
        for (int i = 0; i < 4; i++) {
            int row = tm * 4 + i;
            #pragma unroll
            for (int j = 0; j < 2; j++) {
                int col = tn * 2 + 32 * j;
                float a0, a1; unpack2(acc[i][j], a0, a1);
                float2 hv;
                hv.x = fmaxf(a0 + b1s[col], 0.f);
                hv.y = fmaxf(a1 + b1s[col + 1], 0.f);
                *(float2*)&Hs[row * HSTR + col] = hv;
            }
        }

        // ---- phase 2: Y += H[128x64] @ W2[h0:h0+64, :] ----
        #pragma unroll 1
        for (int ht = 0; ht < 4; ht++) {
            __syncthreads();   // Hs visible (first iter) + W2s reuse
            {
                int hr = tid >> 5, f4 = tid & 31;
                const float* src = &W2[(size_t)(e * HID + h0 + ht * 16 + hr) * OUTS];
                *(float4*)&W2s[hr * 256 + f4 * 4]        = *(const float4*)&src[f4 * 4];
                *(float4*)&W2s[hr * 256 + (f4 + 32) * 4] = *(const float4*)&src[(f4 + 32) * 4];
            }
            __syncthreads();
            #pragma unroll
            for (int h = 0; h < 16; h++) {
                ull wv[8];
                #pragma unroll
                for (int j = 0; j < 8; j++)
                    wv[j] = *(const ull*)&W2s[h * 256 + tn * 2 + 32 * j];
                #pragma unroll
                for (int i = 0; i < 4; i++) {
                    float x = Hs[(tm * 4 + i) * HSTR + ht * 16 + h];
                    ull xx = pack2(x, x);
                    #pragma unroll
                    for (int j = 0; j < 8; j++)
                        yacc[i][j] = ffma2(xx, wv[j], yacc[i][j]);
                }
            }
        }
    }

    // ---- epilogue: + b2, scatter back ----
    #pragma unroll
    for (int i = 0; i < 4; i++) {
        int row = tm * 4 + i;
        if (row < valid) {
            float* dst = Y + (size_t)rowtok[row] * OUTS;
            #pragma unroll
            for (int j = 0; j < 8; j++) {
                int col = tn * 2 + 32 * j;
                float y0, y1; unpack2(yacc[i][j], y0, y1);
                float2 o; o.x = y0 + b2s[col]; o.y = y1 + b2s[col + 1];
                *(float2*)&dst[col] = o;
            }
        }
    }
}

extern "C" void kernel_launch(void* const* d_in, const int* in_sizes, int n_in,
                              void* d_out, int out_size) {
    const float* X  = (const float*)d_in[0];
    const float* W1 = (const float*)d_in[1];
    const float* B1 = (const float*)d_in[2];
    const float* W2 = (const float*)d_in[3];
    const float* B2 = (const float*)d_in[4];
    const int*   ids = (const int*)d_in[5];   // int32 or int64; detected on device
    float* Y = (float*)d_out;

    k_detect<<<1, 1>>>(ids);
    k_hist<<<NFEATS / 256, 256>>>(ids);
    k_scan<<<1, 1>>>();
    k_scatter<<<NFEATS / 256, 256>>>(ids);

    size_t smem = (size_t)(TILE_M * XSTR + TILE_M * HSTR + 32 * 64 + 16 * 256 + 64 + 256) * sizeof(float);
    cudaFuncSetAttribute(k_moe, cudaFuncAttributeMaxDynamicSharedMemorySize, (int)smem);

    dim3 grid(NFEATS / TILE_M, NEXP);   // worst-case tiles per expert; empties exit fast
    k_moe<<<grid, THREADS, smem>>>(X, W1, B1, W2, B2, Y);
}

// round 8
// speedup vs baseline: 1.8000x; 1.7845x over previous
#include <cuda_runtime.h>
#include <cuda_bf16.h>
#include <cstdint>

#define NFEATS 131072
#define INS    256
#define HID    1024
#define OUTS   256
#define NEXP   16
#define TM     128
#define THREADS 256
#define NCH    16          // hidden chunks of 64
#define SLICES_PER_CH 20   // 16 phase1 (k16 of 256) + 4 phase2 (k16 of 64)
#define NSLICES (NCH * SLICES_PER_CH)

#define XSTRB 528   // X smem row stride bytes (264 bf16: 132 words = 4 mod 32 -> conflict-free)
#define HSTRB 144   // H smem row stride bytes (72 bf16: 36 words = 4 mod 32)

// smem layout (bytes)
#define SM_XHI 0
#define SM_XLO 67584
#define SM_HHI 135168
#define SM_HLO 153600
#define SM_W   172032     // 3 slots x 16384
#define SM_B2  221184     // 1024
#define SM_RT  222208     // 512
#define SM_TOT 222720

// ---------------- routing scratch ----------------
__device__ int d_perm[NFEATS];
__device__ int d_counts[NEXP];
__device__ int d_offsets[NEXP + 1];
__device__ int d_cursor[NEXP];
__device__ int d_wide;

// ---------------- split/transposed weights: [E][n][k] bf16 hi/lo ----------------
__device__ __nv_bfloat16 g_w1t_hi[NEXP * HID * INS];
__device__ __nv_bfloat16 g_w1t_lo[NEXP * HID * INS];
__device__ __nv_bfloat16 g_w2t_hi[NEXP * OUTS * HID];
__device__ __nv_bfloat16 g_w2t_lo[NEXP * OUTS * HID];

// ---------------- routing ----------------
__global__ void k_detect(const int* __restrict__ ids) {
    int wide = 1;
    for (int i = 1; i < 64; i += 2) if (ids[i] != 0) { wide = 0; break; }
    d_wide = wide;
    for (int e = 0; e < NEXP; e++) d_counts[e] = 0;
}
__global__ void k_hist(const int* __restrict__ ids) {
    __shared__ int cnt[NEXP];
    int t = threadIdx.x;
    if (t < NEXP) cnt[t] = 0;
    __syncthreads();
    int i = blockIdx.x * blockDim.x + t;
    int id = d_wide ? ids[2 * i] : ids[i];
    atomicAdd(&cnt[id], 1);
    __syncthreads();
    if (t < NEXP) atomicAdd(&d_counts[t], cnt[t]);
}
__global__ void k_scan() {
    int s = 0;
    for (int e = 0; e < NEXP; e++) { d_offsets[e] = s; d_cursor[e] = s; s += d_counts[e]; }
    d_offsets[NEXP] = s;
}
__global__ void k_scatter(const int* __restrict__ ids) {
    __shared__ int lcnt[NEXP], lbase[NEXP];
    int t = threadIdx.x;
    if (t < NEXP) lcnt[t] = 0;
    __syncthreads();
    int i = blockIdx.x * blockDim.x + t;
    int id = d_wide ? ids[2 * i] : ids[i];
    int r = atomicAdd(&lcnt[id], 1);
    __syncthreads();
    if (t < NEXP) lbase[t] = atomicAdd(&d_cursor[t], lcnt[t]);
    __syncthreads();
    d_perm[lbase[id] + r] = i;
}

// ---------------- transpose + bf16 split: src[E][R][C] f32 -> dst[E][C][R] ----------------
__global__ void k_tsplit(const float* __restrict__ src, __nv_bfloat16* __restrict__ dhi,
                         __nv_bfloat16* __restrict__ dlo, int R, int C) {
    __shared__ float t[32][33];
    int e = blockIdx.z, c0 = blockIdx.x * 32, r0 = blockIdx.y * 32;
    const float* s = src + (size_t)e * R * C;
    for (int i = threadIdx.y; i < 32; i += 8)
        t[i][threadIdx.x] = s[(size_t)(r0 + i) * C + c0 + threadIdx.x];
    __syncthreads();
    __nv_bfloat16* ph = dhi + (size_t)e * R * C;
    __nv_bfloat16* pl = dlo + (size_t)e * R * C;
    for (int i = threadIdx.y; i < 32; i += 8) {
        float v = t[threadIdx.x][i];
        __nv_bfloat16 h = __float2bfloat16_rn(v);
        __nv_bfloat16 l = __float2bfloat16_rn(v - __bfloat162float(h));
        size_t o = (size_t)(c0 + i) * R + r0 + threadIdx.x;
        ph[o] = h; pl[o] = l;
    }
}

// ---------------- helpers ----------------
__device__ __forceinline__ uint32_t smem_u32(const void* p) {
    uint32_t a;
    asm("{ .reg .u64 t; cvta.to.shared.u64 t, %1; cvt.u32.u64 %0, t; }" : "=r"(a) : "l"(p));
    return a;
}
#define CPASYNC16(dst, src) \
    asm volatile("cp.async.cg.shared.global [%0], [%1], 16;" :: "r"(dst), "l"(src))
#define CP_COMMIT() asm volatile("cp.async.commit_group;" ::: "memory")
#define CP_WAIT1()  asm volatile("cp.async.wait_group 1;" ::: "memory")

__device__ __forceinline__ uint32_t lds32(uint32_t ad) {
    uint32_t v; asm volatile("ld.shared.b32 %0, [%1];" : "=r"(v) : "r"(ad)); return v;
}
__device__ __forceinline__ void sts32(uint32_t ad, uint32_t v) {
    asm volatile("st.shared.b32 [%0], %1;" :: "r"(ad), "r"(v));
}

// mma.sync m16n8k16 row.col f32.bf16.bf16.f32, D == C (accumulate in place)
__device__ __forceinline__ void mma16816(float* d, const uint32_t* a, const uint32_t* b) {
    asm volatile(
        "mma.sync.aligned.m16n8k16.row.col.f32.bf16.bf16.f32 "
        "{%0,%1,%2,%3}, {%4,%5,%6,%7}, {%8,%9}, {%0,%1,%2,%3};"
        : "+f"(d[0]), "+f"(d[1]), "+f"(d[2]), "+f"(d[3])
        : "r"(a[0]), "r"(a[1]), "r"(a[2]), "r"(a[3]), "r"(b[0]), "r"(b[1]));
}

// A fragment (16x16 bf16, row-major smem): base+row already includes lane group g,
// kbyte includes 2*cp element offset (in bytes).
__device__ __forceinline__ void ldA(uint32_t a[4], uint32_t ad, uint32_t strB) {
    a[0] = lds32(ad);
    a[1] = lds32(ad + 8u * strB);
    a[2] = lds32(ad + 16u);
    a[3] = lds32(ad + 8u * strB + 16u);
}

__device__ __forceinline__ uint32_t pk(float a, float b) {
    return (uint32_t)__bfloat16_as_ushort(__float2bfloat16_rn(a))
         | ((uint32_t)__bfloat16_as_ushort(__float2bfloat16_rn(b)) << 16);
}

__global__ __launch_bounds__(THREADS, 1)
void k_moe(const float* __restrict__ X, const float* __restrict__ B1g,
           const float* __restrict__ B2g, float* __restrict__ Y)
{
    const int e = blockIdx.y;
    const int start = d_offsets[e];
    const int count = d_offsets[e + 1] - start;
    const int m0 = blockIdx.x * TM;
    if (m0 >= count) return;
    const int valid = min(TM, count - m0);

    extern __shared__ char smraw[];
    const uint32_t su = smem_u32(smraw);
    float* b2s = (float*)(smraw + SM_B2);
    int* rowtok = (int*)(smraw + SM_RT);

    const int tid = threadIdx.x;
    const int wid = tid >> 5, lane = tid & 31;
    const int g = lane >> 2, cp = lane & 3;
    // phase1 warp grid 4x2 (D1 = 128x64); phase2 warp grid 2x4 (Y = 128x256)
    const int wm1 = wid >> 1, wn1 = wid & 1;
    const int wm2 = wid >> 2, wn2 = wid & 3;

    if (tid < TM) rowtok[tid] = (tid < valid) ? d_perm[start + m0 + tid] : -1;
    if (tid < OUTS) b2s[tid] = B2g[e * OUTS + tid];
    __syncthreads();

    // ---- gather X -> bf16 hi/lo padded smem (zeros for padded rows) ----
    for (int idx = tid; idx < TM * (INS / 4); idx += THREADS) {
        int r = idx >> 6, c4 = idx & 63;
        float4 v = make_float4(0.f, 0.f, 0.f, 0.f);
        int tok = rowtok[r];
        if (tok >= 0) v = ((const float4*)X)[(size_t)tok * (INS / 4) + c4];
        float hx = __bfloat162float(__float2bfloat16_rn(v.x));
        float hy = __bfloat162float(__float2bfloat16_rn(v.y));
        float hz = __bfloat162float(__float2bfloat16_rn(v.z));
        float hw = __bfloat162float(__float2bfloat16_rn(v.w));
        uint32_t o = (uint32_t)r * XSTRB + (uint32_t)c4 * 8u;
        asm volatile("st.shared.v2.b32 [%0], {%1,%2};" ::
                     "r"(su + SM_XHI + o), "r"(pk(hx, hy)), "r"(pk(hz, hw)));
        asm volatile("st.shared.v2.b32 [%0], {%1,%2};" ::
                     "r"(su + SM_XLO + o), "r"(pk(v.x - hx, v.y - hy)), "r"(pk(v.z - hz, v.w - hw)));
    }

    // accumulators
    float yacc[4][8][4];
    #pragma unroll
    for (int i = 0; i < 4; i++)
        #pragma unroll
        for (int j = 0; j < 8; j++)
            #pragma unroll
            for (int q = 0; q < 4; q++) yacc[i][j][q] = 0.f;
    float p1[2][4][4];
    #pragma unroll
    for (int i = 0; i < 2; i++)
        #pragma unroll
        for (int j = 0; j < 4; j++)
            #pragma unroll
            for (int q = 0; q < 4; q++) p1[i][j][q] = 0.f;

    // ---- W slice prefetch (k16 slices, 3 smem slots, depth-2) ----
    auto prefetch = [&](int S) {
        if (S >= NSLICES) return;
        int c = S / SLICES_PER_CH, ls = S - c * SLICES_PER_CH;
        const __nv_bfloat16 *bh_, *bl_;
        int nrows; uint32_t kb;
        if (ls < 16) {
            size_t off = ((size_t)(e * HID + c * 64)) * INS + ls * 16;
            bh_ = g_w1t_hi + off; bl_ = g_w1t_lo + off;
            nrows = 64; kb = INS * 2;
        } else {
            size_t off = (size_t)(e * OUTS) * HID + c * 64 + (ls - 16) * 16;
            bh_ = g_w2t_hi + off; bl_ = g_w2t_lo + off;
            nrows = 256; kb = HID * 2;
        }
        uint32_t slot = su + SM_W + (uint32_t)(S % 3) * 16384u;
        uint32_t loff = (uint32_t)nrows * 32u;
        int tot = nrows * 4;   // 16B ops across hi+lo
        for (int o = tid; o < tot; o += THREADS) {
            int half = (o >= nrows * 2);
            int r2 = half ? o - nrows * 2 : o;
            int n = r2 >> 1, part = r2 & 1;
            const char* src = (const char*)(half ? bl_ : bh_) + (size_t)n * kb + part * 16;
            CPASYNC16(slot + half * loff + (uint32_t)n * 32u + (uint32_t)part * 16u, src);
        }
    };

    prefetch(0); CP_COMMIT();
    prefetch(1); CP_COMMIT();

    for (int S = 0; S < NSLICES; S++) {
        CP_WAIT1();
        __syncthreads();
        prefetch(S + 2); CP_COMMIT();

        int c = S / SLICES_PER_CH, ls = S - c * SLICES_PER_CH;
        uint32_t slot = su + SM_W + (uint32_t)(S % 3) * 16384u;

        if (ls < 16) {
            // ---- phase1: D1[128x64] += Xsplit @ W1c^T, k16 = ls ----
            uint32_t ah[2][4], al[2][4];
            uint32_t kb2 = (uint32_t)(ls * 16 + 2 * cp) * 2u;
            #pragma unroll
            for (int i = 0; i < 2; i++) {
                uint32_t rb = (uint32_t)(wm1 * 32 + i * 16 + g) * XSTRB + kb2;
                ldA(ah[i], su + SM_XHI + rb, XSTRB);
                ldA(al[i], su + SM_XLO + rb, XSTRB);
            }
            #pragma unroll
            for (int j = 0; j < 4; j++) {
                uint32_t nb = (uint32_t)(wn1 * 32 + j * 8 + g) * 32u + (uint32_t)cp * 4u;
                uint32_t bh[2], bl[2];
                bh[0] = lds32(slot + nb); bh[1] = lds32(slot + nb + 16u);
                bl[0] = lds32(slot + 2048u + nb); bl[1] = lds32(slot + 2048u + nb + 16u);
                #pragma unroll
                for (int i = 0; i < 2; i++) {
                    mma16816(p1[i][j], ah[i], bh);   // hi*hi
                    mma16816(p1[i][j], al[i], bh);   // lo*hi
                    mma16816(p1[i][j], ah[i], bl);   // hi*lo
                }
            }
        } else {
            if (ls == 16) {
                // ---- epilogue chunk c: bias + relu + bf16 split -> H smem ----
                #pragma unroll
                for (int i = 0; i < 2; i++) {
                    #pragma unroll
                    for (int j = 0; j < 4; j++) {
                        int row = wm1 * 32 + i * 16 + g;
                        int col = wn1 * 32 + j * 8 + 2 * cp;
                        float2 bv = *(const float2*)&B1g[e * HID + c * 64 + col];
                        uint32_t ob = (uint32_t)col * 2u;
                        {
                            float h0 = fmaxf(p1[i][j][0] + bv.x, 0.f);
                            float h1 = fmaxf(p1[i][j][1] + bv.y, 0.f);
                            float a0 = __bfloat162float(__float2bfloat16_rn(h0));
                            float a1 = __bfloat162float(__float2bfloat16_rn(h1));
                            uint32_t ad = (uint32_t)row * HSTRB + ob;
                            sts32(su + SM_HHI + ad, pk(h0, h1));
                            sts32(su + SM_HLO + ad, pk(h0 - a0, h1 - a1));
                        }
                        {
                            float h0 = fmaxf(p1[i][j][2] + bv.x, 0.f);
                            float h1 = fmaxf(p1[i][j][3] + bv.y, 0.f);
                            float a0 = __bfloat162float(__float2bfloat16_rn(h0));
                            float a1 = __bfloat162float(__float2bfloat16_rn(h1));
                            uint32_t ad = (uint32_t)(row + 8) * HSTRB + ob;
                            sts32(su + SM_HHI + ad, pk(h0, h1));
                            sts32(su + SM_HLO + ad, pk(h0 - a0, h1 - a1));
                        }
                        #pragma unroll
                        for (int q = 0; q < 4; q++) p1[i][j][q] = 0.f;
                    }
                }
                __syncthreads();
            }
            // ---- phase2: Y[128x256] += Hsplit @ W2c^T, k16 = ls-16 ----
            int t2 = ls - 16;
            uint32_t ah[4][4], al[4][4];
            uint32_t kb2 = (uint32_t)(t2 * 16 + 2 * cp) * 2u;
            #pragma unroll
            for (int i = 0; i < 4; i++) {
                uint32_t rb = (uint32_t)(wm2 * 64 + i * 16 + g) * HSTRB + kb2;
                ldA(ah[i], su + SM_HHI + rb, HSTRB);
                ldA(al[i], su + SM_HLO + rb, HSTRB);
            }
            #pragma unroll
            for (int j = 0; j < 8; j++) {
                uint32_t nb = (uint32_t)(wn2 * 64 + j * 8 + g) * 32u + (uint32_t)cp * 4u;
                uint32_t bh[2], bl[2];
                bh[0] = lds32(slot + nb); bh[1] = lds32(slot + nb + 16u);
                bl[0] = lds32(slot + 8192u + nb); bl[1] = lds32(slot + 8192u + nb + 16u);
                #pragma unroll
                for (int i = 0; i < 4; i++) {
                    mma16816(yacc[i][j], ah[i], bh);   // hi*hi
                    mma16816(yacc[i][j], al[i], bh);   // lo*hi
                    mma16816(yacc[i][j], ah[i], bl);   // hi*lo
                }
            }
        }
    }

    // ---- final: Y frags + b2 -> gmem scatter ----
    #pragma unroll
    for (int i = 0; i < 4; i++) {
        int row = wm2 * 64 + i * 16 + g;
        int tokA = rowtok[row];
        int tokB = rowtok[row + 8];
        #pragma unroll
        for (int j = 0; j < 8; j++) {
            int col = wn2 * 64 + j * 8 + 2 * cp;
            if (tokA >= 0) {
                float2 o;
                o.x = yacc[i][j][0] + b2s[col];
                o.y = yacc[i][j][1] + b2s[col + 1];
                *(float2*)&Y[(size_t)tokA * OUTS + col] = o;
            }
            if (tokB >= 0) {
                float2 o;
                o.x = yacc[i][j][2] + b2s[col];
                o.y = yacc[i][j][3] + b2s[col + 1];
                *(float2*)&Y[(size_t)tokB * OUTS + col] = o;
            }
        }
    }
}

extern "C" void kernel_launch(void* const* d_in, const int* in_sizes, int n_in,
                              void* d_out, int out_size) {
    const float* X  = (const float*)d_in[0];
    const float* W1 = (const float*)d_in[1];
    const float* B1 = (const float*)d_in[2];
    const float* W2 = (const float*)d_in[3];
    const float* B2 = (const float*)d_in[4];
    const int* ids  = (const int*)d_in[5];
    float* Y = (float*)d_out;

    k_detect<<<1, 1>>>(ids);
    k_hist<<<NFEATS / 256, 256>>>(ids);
    k_scan<<<1, 1>>>();
    k_scatter<<<NFEATS / 256, 256>>>(ids);

    __nv_bfloat16 *w1h, *w1l, *w2h, *w2l;
    cudaGetSymbolAddress((void**)&w1h, g_w1t_hi);
    cudaGetSymbolAddress((void**)&w1l, g_w1t_lo);
    cudaGetSymbolAddress((void**)&w2h, g_w2t_hi);
    cudaGetSymbolAddress((void**)&w2l, g_w2t_lo);
    dim3 tb(32, 8);
    k_tsplit<<<dim3(HID / 32, INS / 32, NEXP), tb>>>(W1, w1h, w1l, INS, HID);
    k_tsplit<<<dim3(OUTS / 32, HID / 32, NEXP), tb>>>(W2, w2h, w2l, HID, OUTS);

    cudaFuncSetAttribute(k_moe, cudaFuncAttributeMaxDynamicSharedMemorySize, SM_TOT);
    dim3 grid(NFEATS / TM, NEXP);
    k_moe<<<grid, THREADS, SM_TOT>>>(X, B1, B2, Y);
}

// round 9
// speedup vs baseline: 2.9481x; 1.6378x over previous
#include <cuda_runtime.h>
#include <cuda_bf16.h>
#include <cstdint>

#define NFEATS 131072
#define INS    256
#define HID    1024
#define OUTS   256
#define NEXP   16
#define TM     128
#define THREADS 256
#define MAXT   (NFEATS / TM + NEXP)     // 1040 tile upper bound
#define SPC    12                        // slices per chunk: 8 phase1(k32) + 4 phase2(k16)
#define NSLICES (16 * SPC)               // 192

#define XSTRB 1040   // X smem row stride bytes (260 fp32; 4 mod 32 banks -> conflict-free)
#define HSTRB 272    // H smem row stride bytes (68 fp32)
#define W1STR 144    // phase1 W slab row stride (36 words; 4 mod 32)
#define W2STR 80     // phase2 W slab row stride (20 words; bank-distinct over g)

// smem layout (bytes)
#define SM_X   0                          // 128*1040 = 133120
#define SM_H   133120                     // 128*272  = 34816
#define SM_W   167936                     // 3 slots x 20480
#define SM_B2  229376                     // 1024
#define SM_RT  230400                     // 512
#define SM_TOT 230912

// ---------------- device scratch ----------------
__device__ int d_perm[NFEATS];
__device__ int d_counts[NEXP];
__device__ int d_offsets[NEXP + 1];
__device__ int d_cursor[NEXP];
__device__ int d_tile_e[MAXT];
__device__ int d_tile_s[MAXT];
__device__ int d_tile_v[MAXT];
__device__ int d_ntiles;

// tf32-rounded transposed weights, stored as fp32: [E][n][k]
__device__ float g_w1t[NEXP * HID * INS];
__device__ float g_w2t[NEXP * OUTS * HID];

// ---------------- helpers ----------------
__device__ __forceinline__ uint32_t smem_u32(const void* p) {
    uint32_t a;
    asm("{ .reg .u64 t; cvta.to.shared.u64 t, %1; cvt.u32.u64 %0, t; }" : "=r"(a) : "l"(p));
    return a;
}
__device__ __forceinline__ uint32_t tf32r(float v) {
    uint32_t o; asm("cvt.rna.tf32.f32 %0, %1;" : "=r"(o) : "f"(v)); return o;
}
#define CPASYNC16(dst, src) \
    asm volatile("cp.async.cg.shared.global [%0], [%1], 16;" :: "r"(dst), "l"(src))
#define CP_COMMIT() asm volatile("cp.async.commit_group;" ::: "memory")
#define CP_WAIT1()  asm volatile("cp.async.wait_group 1;" ::: "memory")

__device__ __forceinline__ uint32_t lds32(uint32_t ad) {
    uint32_t v; asm volatile("ld.shared.b32 %0, [%1];" : "=r"(v) : "r"(ad)); return v;
}

// mma m16n8k8 tf32, D==C accumulate in place
__device__ __forceinline__ void mmatf(float* d, const uint32_t* a, uint32_t b0, uint32_t b1) {
    asm volatile(
        "mma.sync.aligned.m16n8k8.row.col.f32.tf32.tf32.f32 "
        "{%0,%1,%2,%3}, {%4,%5,%6,%7}, {%8,%9}, {%0,%1,%2,%3};"
        : "+f"(d[0]), "+f"(d[1]), "+f"(d[2]), "+f"(d[3])
        : "r"(a[0]), "r"(a[1]), "r"(a[2]), "r"(a[3]), "r"(b0), "r"(b1));
}
// A fragment m16k8: a0=(g,cp) a1=(g+8,cp) a2=(g,cp+4) a3=(g+8,cp+4)
__device__ __forceinline__ void ldA(uint32_t a[4], uint32_t ad, uint32_t strB) {
    a[0] = lds32(ad);
    a[1] = lds32(ad + 8u * strB);
    a[2] = lds32(ad + 16u);
    a[3] = lds32(ad + 8u * strB + 16u);
}

// ---------------- routing ----------------
__global__ void k_hist(const int* __restrict__ ids) {
    __shared__ int cnt[NEXP];
    int t = threadIdx.x;
    if (t < NEXP) cnt[t] = 0;
    // inline int64-vs-int32 detection (every block computes it; idempotent)
    if (t == 0 && blockIdx.x == 0) {
        int wide = 1;
        for (int i = 1; i < 128; i += 2) if (ids[i] != 0) { wide = 0; break; }
        d_wide_store: ;
        *(volatile int*)&d_counts[0] += 0;  // no-op keep
    }
    __syncthreads();
    // detection must be visible before indexing: compute locally per block instead
    int wide = 1;
    #pragma unroll
    for (int i = 1; i < 17; i += 2) if (ids[i] != 0) wide = 0;
    if (wide) { for (int i = 17; i < 128; i += 2) if (ids[i] != 0) { wide = 0; break; } }
    int i = blockIdx.x * blockDim.x + t;
    int id = wide ? ids[2 * i] : ids[i];
    atomicAdd(&cnt[id], 1);
    __syncthreads();
    if (t < NEXP) atomicAdd(&d_counts[t], cnt[t]);
}
__global__ void k_scan() {
    int s = 0, tn = 0;
    for (int e = 0; e < NEXP; e++) {
        int c = d_counts[e];
        d_offsets[e] = s; d_cursor[e] = s;
        for (int m0 = 0; m0 < c; m0 += TM) {
            d_tile_e[tn] = e; d_tile_s[tn] = s + m0;
            d_tile_v[tn] = min(TM, c - m0); tn++;
        }
        s += c;
    }
    d_offsets[NEXP] = s;
    d_ntiles = tn;
}
__global__ void k_scatter(const int* __restrict__ ids) {
    __shared__ int lcnt[NEXP], lbase[NEXP];
    int t = threadIdx.x;
    if (t < NEXP) lcnt[t] = 0;
    __syncthreads();
    int wide = 1;
    #pragma unroll
    for (int i = 1; i < 17; i += 2) if (ids[i] != 0) wide = 0;
    if (wide) { for (int i = 17; i < 128; i += 2) if (ids[i] != 0) { wide = 0; break; } }
    int i = blockIdx.x * blockDim.x + t;
    int id = wide ? ids[2 * i] : ids[i];
    int r = atomicAdd(&lcnt[id], 1);
    __syncthreads();
    if (t < NEXP) lbase[t] = atomicAdd(&d_cursor[t], lcnt[t]);
    __syncthreads();
    d_perm[lbase[id] + r] = i;
    // re-zero counts for the next graph replay (no later reader this run)
    if (blockIdx.x == 0 && t < NEXP) d_counts[t] = 0;
}

// ---------------- transpose + tf32 round: src[E][R][C] f32 -> dst[E][C][R] ----------------
__global__ void k_trnd(const float* __restrict__ src, float* __restrict__ dst, int R, int C) {
    __shared__ float t[32][33];
    int e = blockIdx.z, c0 = blockIdx.x * 32, r0 = blockIdx.y * 32;
    const float* s = src + (size_t)e * R * C;
    for (int i = threadIdx.y; i < 32; i += 8)
        t[i][threadIdx.x] = s[(size_t)(r0 + i) * C + c0 + threadIdx.x];
    __syncthreads();
    float* p = dst + (size_t)e * R * C;
    for (int i = threadIdx.y; i < 32; i += 8) {
        float v = t[threadIdx.x][i];
        p[(size_t)(c0 + i) * R + r0 + threadIdx.x] = __uint_as_float(tf32r(v));
    }
}

// ---------------- fused MoE tile kernel (tf32 tensor cores) ----------------
__global__ __launch_bounds__(THREADS, 1)
void k_moe(const float* __restrict__ X, const float* __restrict__ B1g,
           const float* __restrict__ B2g, float* __restrict__ Y)
{
    const int bx = blockIdx.x;
    if (bx >= d_ntiles) return;
    const int e = d_tile_e[bx];
    const int s0 = d_tile_s[bx];
    const int valid = d_tile_v[bx];

    extern __shared__ char smraw[];
    const uint32_t su = smem_u32(smraw);
    float* b2s = (float*)(smraw + SM_B2);
    int* rowtok = (int*)(smraw + SM_RT);

    const int tid = threadIdx.x;
    const int wid = tid >> 5, lane = tid & 31;
    const int g = lane >> 2, cp = lane & 3;
    const int wm1 = wid >> 1, wn1 = wid & 1;   // phase1 grid 4x2 over D1 128x64
    const int wm2 = wid >> 2, wn2 = wid & 3;   // phase2 grid 2x4 over Y 128x256

    if (tid < TM) rowtok[tid] = (tid < valid) ? d_perm[s0 + tid] : -1;
    if (tid < OUTS) b2s[tid] = B2g[e * OUTS + tid];
    __syncthreads();

    // gather X -> tf32-rounded fp32 smem (zeros for padded rows)
    for (int idx = tid; idx < TM * (INS / 4); idx += THREADS) {
        int r = idx >> 6, c4 = idx & 63;
        float4 v = make_float4(0.f, 0.f, 0.f, 0.f);
        int tok = rowtok[r];
        if (tok >= 0) v = ((const float4*)X)[(size_t)tok * (INS / 4) + c4];
        uint32_t o = su + SM_X + (uint32_t)r * XSTRB + (uint32_t)c4 * 16u;
        asm volatile("st.shared.v4.b32 [%0], {%1,%2,%3,%4};" ::
                     "r"(o), "r"(tf32r(v.x)), "r"(tf32r(v.y)), "r"(tf32r(v.z)), "r"(tf32r(v.w)));
    }

    float yacc[4][8][4];
    #pragma unroll
    for (int i = 0; i < 4; i++)
        #pragma unroll
        for (int j = 0; j < 8; j++)
            #pragma unroll
            for (int q = 0; q < 4; q++) yacc[i][j][q] = 0.f;
    float p1[2][4][4];
    #pragma unroll
    for (int i = 0; i < 2; i++)
        #pragma unroll
        for (int j = 0; j < 4; j++)
            #pragma unroll
            for (int q = 0; q < 4; q++) p1[i][j][q] = 0.f;

    // W slice prefetch into 3 smem slots, depth-2
    auto prefetch = [&](int S) {
        if (S >= NSLICES) return;
        int c = S / SPC, sc = S - c * SPC;
        uint32_t slot = su + SM_W + (uint32_t)(S % 3) * 20480u;
        if (sc < 8) {           // phase1: 64 rows x 32 fp32 (128B), stride 144B
            const float* base = g_w1t + ((size_t)(e * HID + c * 64)) * INS + sc * 32;
            #pragma unroll
            for (int o = 0; o < 2; o++) {
                int op = tid + o * 256;           // 512 ops
                int n = op >> 3, part = op & 7;
                CPASYNC16(slot + (uint32_t)n * W1STR + (uint32_t)part * 16u,
                          (const char*)(base + (size_t)n * INS) + part * 16);
            }
        } else {                // phase2: 256 rows x 16 fp32 (64B), stride 80B
            int t2 = sc - 8;
            const float* base = g_w2t + (size_t)(e * OUTS) * HID + c * 64 + t2 * 16;
            #pragma unroll
            for (int o = 0; o < 4; o++) {
                int op = tid + o * 256;           // 1024 ops
                int n = op >> 2, part = op & 3;
                CPASYNC16(slot + (uint32_t)n * W2STR + (uint32_t)part * 16u,
                          (const char*)(base + (size_t)n * HID) + part * 16);
            }
        }
    };

    prefetch(0); CP_COMMIT();
    prefetch(1); CP_COMMIT();

    for (int S = 0; S < NSLICES; S++) {
        CP_WAIT1();
        __syncthreads();
        prefetch(S + 2); CP_COMMIT();

        const int c = S / SPC, sc = S - c * SPC;
        const uint32_t slot = su + SM_W + (uint32_t)(S % 3) * 20480u;

        if (sc < 8) {
            // phase1: D1[128x64] += X[128x256] @ W1c^T, k32 slice
            #pragma unroll
            for (int k8 = 0; k8 < 4; k8++) {
                uint32_t kb = (uint32_t)((sc * 32 + k8 * 8 + cp) * 4);
                uint32_t a[2][4];
                #pragma unroll
                for (int i = 0; i < 2; i++)
                    ldA(a[i], su + SM_X + (uint32_t)(wm1 * 32 + i * 16 + g) * XSTRB + kb, XSTRB);
                #pragma unroll
                for (int j = 0; j < 4; j++) {
                    uint32_t nb = slot + (uint32_t)(wn1 * 32 + j * 8 + g) * W1STR
                                + (uint32_t)((k8 * 8 + cp) * 4);
                    uint32_t b0 = lds32(nb), b1 = lds32(nb + 16u);
                    mmatf(p1[0][j], a[0], b0, b1);
                    mmatf(p1[1][j], a[1], b0, b1);
                }
            }
        } else {
            if (sc == 8) {
                // epilogue chunk c: bias + relu + tf32 round -> H smem
                #pragma unroll
                for (int i = 0; i < 2; i++) {
                    #pragma unroll
                    for (int j = 0; j < 4; j++) {
                        int row = wm1 * 32 + i * 16 + g;
                        int col = wn1 * 32 + j * 8 + 2 * cp;
                        float2 bv = *(const float2*)&B1g[e * HID + c * 64 + col];
                        uint32_t ad0 = su + SM_H + (uint32_t)row * HSTRB + (uint32_t)col * 4u;
                        asm volatile("st.shared.v2.b32 [%0], {%1,%2};" :: "r"(ad0),
                            "r"(tf32r(fmaxf(p1[i][j][0] + bv.x, 0.f))),
                            "r"(tf32r(fmaxf(p1[i][j][1] + bv.y, 0.f))));
                        uint32_t ad1 = su + SM_H + (uint32_t)(row + 8) * HSTRB + (uint32_t)col * 4u;
                        asm volatile("st.shared.v2.b32 [%0], {%1,%2};" :: "r"(ad1),
                            "r"(tf32r(fmaxf(p1[i][j][2] + bv.x, 0.f))),
                            "r"(tf32r(fmaxf(p1[i][j][3] + bv.y, 0.f))));
                        #pragma unroll
                        for (int q = 0; q < 4; q++) p1[i][j][q] = 0.f;
                    }
                }
                __syncthreads();
            }
            // phase2: Y[128x256] += H[128x64] @ W2c^T, k16 slice
            const int t2 = sc - 8;
            #pragma unroll
            for (int k8 = 0; k8 < 2; k8++) {
                uint32_t kb = (uint32_t)((t2 * 16 + k8 * 8 + cp) * 4);
                uint32_t a[4][4];
                #pragma unroll
                for (int i = 0; i < 4; i++)
                    ldA(a[i], su + SM_H + (uint32_t)(wm2 * 64 + i * 16 + g) * HSTRB + kb, HSTRB);
                #pragma unroll
                for (int j = 0; j < 8; j++) {
                    uint32_t nb = slot + (uint32_t)(wn2 * 64 + j * 8 + g) * W2STR
                                + (uint32_t)((k8 * 8 + cp) * 4);
                    uint32_t b0 = lds32(nb), b1 = lds32(nb + 16u);
                    #pragma unroll
                    for (int i = 0; i < 4; i++) mmatf(yacc[i][j], a[i], b0, b1);
                }
            }
        }
    }

    // final: Y frags + b2 -> gmem scatter
    #pragma unroll
    for (int i = 0; i < 4; i++) {
        int row = wm2 * 64 + i * 16 + g;
        int tokA = rowtok[row];
        int tokB = rowtok[row + 8];
        #pragma unroll
        for (int j = 0; j < 8; j++) {
            int col = wn2 * 64 + j * 8 + 2 * cp;
            if (tokA >= 0) {
                float2 o;
                o.x = yacc[i][j][0] + b2s[col];
                o.y = yacc[i][j][1] + b2s[col + 1];
                *(float2*)&Y[(size_t)tokA * OUTS + col] = o;
            }
            if (tokB >= 0) {
                float2 o;
                o.x = yacc[i][j][2] + b2s[col];
                o.y = yacc[i][j][3] + b2s[col + 1];
                *(float2*)&Y[(size_t)tokB * OUTS + col] = o;
            }
        }
    }
}

extern "C" void kernel_launch(void* const* d_in, const int* in_sizes, int n_in,
                              void* d_out, int out_size) {
    const float* X  = (const float*)d_in[0];
    const float* W1 = (const float*)d_in[1];
    const float* B1 = (const float*)d_in[2];
    const float* W2 = (const float*)d_in[3];
    const float* B2 = (const float*)d_in[4];
    const int* ids  = (const int*)d_in[5];
    float* Y = (float*)d_out;

    // launch order keeps k_moe at index 6 (1-based) for the ncu -s 5 -c 1 capture
    k_hist<<<NFEATS / 256, 256>>>(ids);
    k_scan<<<1, 1>>>();
    k_scatter<<<NFEATS / 256, 256>>>(ids);

    float *w1t, *w2t;
    cudaGetSymbolAddress((void**)&w1t, g_w1t);
    cudaGetSymbolAddress((void**)&w2t, g_w2t);
    dim3 tb(32, 8);
    k_trnd<<<dim3(HID / 32, INS / 32, NEXP), tb>>>(W1, w1t, INS, HID);
    k_trnd<<<dim3(OUTS / 32, HID / 32, NEXP), tb>>>(W2, w2t, HID, OUTS);

    cudaFuncSetAttribute(k_moe, cudaFuncAttributeMaxDynamicSharedMemorySize, SM_TOT);
    k_moe<<<MAXT, THREADS, SM_TOT>>>(X, B1, B2, Y);
}